// round 5
// baseline (speedup 1.0000x reference)
#include <cuda_runtime.h>
#include <cuda_bf16.h>
#include <math.h>
#include <cstdint>

#define SDIM 4096
#define CDIM 256
#define EDIM 128
#define NBATCH 4

// ---- scratch (device globals: allocation-free) ----
__device__ __nv_bfloat16 g_tp[(size_t)NBATCH * SDIM * (2 * EDIM)]; // [n][s][0:128)=theta [128:256)=phi
__device__ __nv_bfloat16 g_f [(size_t)NBATCH * SDIM * SDIM];       // unnormalized exp(logits)
__device__ __nv_bfloat16 g_xb[(size_t)NBATCH * CDIM * SDIM];       // x bf16 [n][c][s]
__device__ __nv_bfloat16 g_yb[(size_t)NBATCH * SDIM * CDIM];       // y bf16 [n][s][c]
__device__ __nv_bfloat16 g_w2[256 * 256];                          // rows 0-127 theta_w, 128-255 phi_w
__device__ __nv_bfloat16 g_w3[256 * 256];                          // proj_w bf16 [o][c]
__device__ float         g_Z [(size_t)NBATCH * SDIM];              // row sums

// ============================ low-level helpers ============================
__device__ __forceinline__ uint32_t smem_u32(const void* p) {
    uint32_t a;
    asm("{ .reg .u64 t; cvta.to.shared.u64 t, %1; cvt.u32.u64 %0, t; }" : "=r"(a) : "l"(p));
    return a;
}
__device__ __forceinline__ void ldsm4(uint32_t r[4], uint32_t addr) {
    asm volatile("ldmatrix.sync.aligned.m8n8.x4.shared.b16 {%0,%1,%2,%3}, [%4];"
                 : "=r"(r[0]), "=r"(r[1]), "=r"(r[2]), "=r"(r[3]) : "r"(addr));
}
__device__ __forceinline__ void ldsm4t(uint32_t r[4], uint32_t addr) {
    asm volatile("ldmatrix.sync.aligned.m8n8.x4.trans.shared.b16 {%0,%1,%2,%3}, [%4];"
                 : "=r"(r[0]), "=r"(r[1]), "=r"(r[2]), "=r"(r[3]) : "r"(addr));
}
__device__ __forceinline__ void mma16816(float c[4], const uint32_t a[4], uint32_t b0, uint32_t b1) {
    asm volatile("mma.sync.aligned.m16n8k16.row.col.f32.bf16.bf16.f32 "
                 "{%0,%1,%2,%3},{%4,%5,%6,%7},{%8,%9},{%0,%1,%2,%3};"
                 : "+f"(c[0]), "+f"(c[1]), "+f"(c[2]), "+f"(c[3])
                 : "r"(a[0]), "r"(a[1]), "r"(a[2]), "r"(a[3]), "r"(b0), "r"(b1));
}
__device__ __forceinline__ void cp16(uint32_t saddr, const void* g) {
    asm volatile("cp.async.cg.shared.global [%0], [%1], 16;" :: "r"(saddr), "l"(g));
}
#define CP_COMMIT() asm volatile("cp.async.commit_group;" ::: "memory")
#define CP_WAIT(N)  asm volatile("cp.async.wait_group %0;" :: "n"(N) : "memory")

// R rows x 64 cols bf16 (128B rows), XOR-16B swizzle keyed on row&7. NT threads.
template<int R, int NT>
__device__ __forceinline__ void load_tileT(uint32_t sdst, const __nv_bfloat16* g, int ldg) {
    const int tid = threadIdx.x;
    #pragma unroll
    for (int i = 0; i < (R * 8) / NT; i++) {
        const int c = tid + i * NT;
        const int r = c >> 3, kc = c & 7;
        const uint32_t so = sdst + r * 128 + (((uint32_t)kc * 16) ^ ((r & 7) * 16));
        cp16(so, g + (size_t)r * ldg + kc * 8);
    }
}
// 64 rows x 128 cols bf16 (256B rows), 256 threads (for trans-A path).
__device__ __forceinline__ void load_tile_64x128(uint32_t sdst, const __nv_bfloat16* g, int ldg) {
    const int tid = threadIdx.x;
    #pragma unroll
    for (int i = 0; i < 4; i++) {
        const int c = tid + i * 256;
        const int r = c >> 4, kc = c & 15;
        const uint32_t so = sdst + r * 256 + (((uint32_t)kc * 16) ^ ((r & 7) * 16));
        cp16(so, g + (size_t)r * ldg + kc * 8);
    }
}

// acc += A(rows m_base..m_base+63 of smem tile, 128B rows) * B(rows n_base..n_base+31)^T
__device__ __forceinline__ void compute_chunk(uint32_t sA, uint32_t sB,
                                              int m_base, int n_base, int lane,
                                              float acc[4][4][4]) {
    #pragma unroll
    for (int ks = 0; ks < 4; ks++) {
        const int kc = ks * 2 + (lane >> 4);
        uint32_t a[4][4];
        #pragma unroll
        for (int mi = 0; mi < 4; mi++) {
            const int row = m_base + mi * 16 + (lane & 15);
            ldsm4(a[mi], sA + row * 128 + (((uint32_t)kc * 16) ^ ((row & 7) * 16)));
        }
        uint32_t b[4][2];
        #pragma unroll
        for (int nh = 0; nh < 2; nh++) {
            const int row = n_base + nh * 16 + (lane & 15);
            uint32_t r4[4];
            ldsm4(r4, sB + row * 128 + (((uint32_t)kc * 16) ^ ((row & 7) * 16)));
            b[nh * 2 + 0][0] = r4[0]; b[nh * 2 + 0][1] = r4[2];
            b[nh * 2 + 1][0] = r4[1]; b[nh * 2 + 1][1] = r4[3];
        }
        #pragma unroll
        for (int mi = 0; mi < 4; mi++)
            #pragma unroll
            for (int ni = 0; ni < 4; ni++)
                mma16816(acc[mi][ni], a[mi], b[ni][0], b[ni][1]);
    }
}

// acc += At(64x128 smem tile [k][m], 256B rows)^T * B, A fragments via ldmatrix.trans
__device__ __forceinline__ void compute_chunk_At(uint32_t sA, uint32_t sB,
                                                 int wm, int wn, int lane,
                                                 float acc[4][4][4]) {
    #pragma unroll
    for (int ks = 0; ks < 4; ks++) {
        uint32_t a[4][4];
        const int crow_l = ks * 16 + (lane & 7) + ((lane >> 4) & 1) * 8;
        #pragma unroll
        for (int mi = 0; mi < 4; mi++) {
            const int scol = wm * 64 + mi * 16 + ((lane >> 3) & 1) * 8;
            ldsm4t(a[mi], sA + crow_l * 256 + ((((uint32_t)scol >> 3) * 16) ^ ((crow_l & 7) * 16)));
        }
        const int kc = ks * 2 + (lane >> 4);
        uint32_t b[4][2];
        #pragma unroll
        for (int nh = 0; nh < 2; nh++) {
            const int row = wn * 32 + nh * 16 + (lane & 15);
            uint32_t r4[4];
            ldsm4(r4, sB + row * 128 + (((uint32_t)kc * 16) ^ ((row & 7) * 16)));
            b[nh * 2 + 0][0] = r4[0]; b[nh * 2 + 0][1] = r4[2];
            b[nh * 2 + 1][0] = r4[1]; b[nh * 2 + 1][1] = r4[3];
        }
        #pragma unroll
        for (int mi = 0; mi < 4; mi++)
            #pragma unroll
            for (int ni = 0; ni < 4; ni++)
                mma16816(acc[mi][ni], a[mi], b[ni][0], b[ni][1]);
    }
}

#define ZERO_ACC(acc) do { \
    _Pragma("unroll") for (int _a = 0; _a < 4; _a++) \
    _Pragma("unroll") for (int _b = 0; _b < 4; _b++) \
    _Pragma("unroll") for (int _c = 0; _c < 4; _c++) acc[_a][_b][_c] = 0.0f; } while (0)

// ============================ prep ============================
__global__ __launch_bounds__(256) void prep_bf16(const float4* __restrict__ x,
                                                 const float4* __restrict__ theta_w,
                                                 const float4* __restrict__ phi_w,
                                                 const float4* __restrict__ proj_w,
                                                 uint2* __restrict__ xb,
                                                 uint2* __restrict__ w2,
                                                 uint2* __restrict__ w3,
                                                 float* __restrict__ Z, int n4)
{
    const int gt = blockIdx.x * blockDim.x + threadIdx.x;
    const int stride = gridDim.x * blockDim.x;
    if (gt < NBATCH * SDIM) Z[gt] = 0.0f;
    for (int i = gt; i < n4; i += stride) {
        float4 v = x[i];
        __nv_bfloat162 a = __floats2bfloat162_rn(v.x, v.y);
        __nv_bfloat162 b = __floats2bfloat162_rn(v.z, v.w);
        xb[i] = make_uint2(*reinterpret_cast<uint32_t*>(&a), *reinterpret_cast<uint32_t*>(&b));
    }
    if (gt < 8192) {
        float4 v = theta_w[gt];
        __nv_bfloat162 a = __floats2bfloat162_rn(v.x, v.y);
        __nv_bfloat162 b = __floats2bfloat162_rn(v.z, v.w);
        w2[gt] = make_uint2(*reinterpret_cast<uint32_t*>(&a), *reinterpret_cast<uint32_t*>(&b));
        v = phi_w[gt];
        a = __floats2bfloat162_rn(v.x, v.y);
        b = __floats2bfloat162_rn(v.z, v.w);
        w2[8192 + gt] = make_uint2(*reinterpret_cast<uint32_t*>(&a), *reinterpret_cast<uint32_t*>(&b));
    }
    if (gt < 16384) {
        float4 v = proj_w[gt];
        __nv_bfloat162 a = __floats2bfloat162_rn(v.x, v.y);
        __nv_bfloat162 b = __floats2bfloat162_rn(v.z, v.w);
        w3[gt] = make_uint2(*reinterpret_cast<uint32_t*>(&a), *reinterpret_cast<uint32_t*>(&b));
    }
}

// ============================ theta/phi projection (HMMA trans-A, 256 thr) ============================
#define SA2(st) ((uint32_t)((st) * 32768))
#define SB2(st) ((uint32_t)((st) * 32768 + 16384))
__global__ __launch_bounds__(256)
void thetaphi_hmma(const __nv_bfloat16* __restrict__ xb,
                   const __nv_bfloat16* __restrict__ w2,
                   __nv_bfloat16* __restrict__ tp)
{
    extern __shared__ char smem[];
    const uint32_t sb = smem_u32(smem);
    const int tid = threadIdx.x, lane = tid & 31, wid = tid >> 5;
    const int wm = wid & 1, wn = wid >> 1;
    const int z = blockIdx.z, m0 = blockIdx.y * 128, n0 = blockIdx.x * 128;

    const __nv_bfloat16* Abase = xb + (size_t)z * CDIM * SDIM + m0;
    const __nv_bfloat16* Bbase = w2 + (size_t)n0 * 256;

    float acc[4][4][4];
    ZERO_ACC(acc);

    load_tile_64x128(sb + SA2(0), Abase, SDIM);
    load_tileT<128, 256>(sb + SB2(0), Bbase, 256);
    CP_COMMIT();

    const int KT = 4;
    #pragma unroll
    for (int kt = 0; kt < KT; kt++) {
        if (kt + 1 < KT) {
            load_tile_64x128(sb + SA2((kt + 1) & 1), Abase + (size_t)(kt + 1) * 64 * SDIM, SDIM);
            load_tileT<128, 256>(sb + SB2((kt + 1) & 1), Bbase + (kt + 1) * 64, 256);
            CP_COMMIT();
            CP_WAIT(1);
        } else {
            CP_WAIT(0);
        }
        __syncthreads();
        compute_chunk_At(sb + SA2(kt & 1), sb + SB2(kt & 1), wm, wn, lane, acc);
        __syncthreads();
    }

    const int lrow = lane >> 2, lcol2 = (lane & 3) * 2;
    #pragma unroll
    for (int mi = 0; mi < 4; mi++) {
        const int gr0 = m0 + wm * 64 + mi * 16 + lrow;
        #pragma unroll
        for (int ni = 0; ni < 4; ni++) {
            const int col = n0 + wn * 32 + ni * 8 + lcol2;
            __nv_bfloat162 h0 = __floats2bfloat162_rn(acc[mi][ni][0], acc[mi][ni][1]);
            __nv_bfloat162 h1 = __floats2bfloat162_rn(acc[mi][ni][2], acc[mi][ni][3]);
            *reinterpret_cast<uint32_t*>(tp + ((size_t)z * SDIM + gr0) * 256 + col) =
                *reinterpret_cast<uint32_t*>(&h0);
            *reinterpret_cast<uint32_t*>(tp + ((size_t)z * SDIM + gr0 + 8) * 256 + col) =
                *reinterpret_cast<uint32_t*>(&h1);
        }
    }
}

// ============================ fused logits + exp (HMMA, 512 thr, 256x128 tile) ============================
// smem: stage st -> A(256x64,32KB) @ st*49152, B(128x64,16KB) @ st*49152+32768
#define LSA(st) ((uint32_t)((st) * 49152))
#define LSB(st) ((uint32_t)((st) * 49152 + 32768))
__global__ __launch_bounds__(512)
void logits_exp_hmma(const __nv_bfloat16* __restrict__ tp,
                     __nv_bfloat16* __restrict__ f,
                     float* __restrict__ Z)
{
    extern __shared__ char smem[];
    const uint32_t sb = smem_u32(smem);
    const int tid = threadIdx.x, lane = tid & 31, wid = tid >> 5;
    const int wm = wid & 3, wn = wid >> 2;   // 4x4 warp grid: 64-row x 32-col warp tiles
    const int z = blockIdx.z, m0 = blockIdx.y * 256, n0 = blockIdx.x * 128;

    const __nv_bfloat16* Abase = tp + ((size_t)(z * SDIM + m0)) * 256;        // theta, 256 rows
    const __nv_bfloat16* Bbase = tp + ((size_t)(z * SDIM + n0)) * 256 + 128;  // phi, 128 rows

    float acc[4][4][4];
    ZERO_ACC(acc);

    load_tileT<256, 512>(sb + LSA(0), Abase, 256);
    load_tileT<128, 512>(sb + LSB(0), Bbase, 256);
    CP_COMMIT();
    load_tileT<256, 512>(sb + LSA(1), Abase + 64, 256);
    load_tileT<128, 512>(sb + LSB(1), Bbase + 64, 256);
    CP_COMMIT();

    CP_WAIT(1);
    __syncthreads();
    compute_chunk(sb + LSA(0), sb + LSB(0), wm * 64, wn * 32, lane, acc);
    CP_WAIT(0);
    __syncthreads();
    compute_chunk(sb + LSA(1), sb + LSB(1), wm * 64, wn * 32, lane, acc);

    const float alpha = 0.08838834764831845f;
    const int lrow = lane >> 2, lcol2 = (lane & 3) * 2;
    #pragma unroll
    for (int mi = 0; mi < 4; mi++) {
        const int gr0 = m0 + wm * 64 + mi * 16 + lrow;
        const int gr1 = gr0 + 8;
        float rs0 = 0.0f, rs1 = 0.0f;
        #pragma unroll
        for (int ni = 0; ni < 4; ni++) {
            const int col = n0 + wn * 32 + ni * 8 + lcol2;
            float e00 = __expf(acc[mi][ni][0] * alpha);
            float e01 = __expf(acc[mi][ni][1] * alpha);
            float e10 = __expf(acc[mi][ni][2] * alpha);
            float e11 = __expf(acc[mi][ni][3] * alpha);
            rs0 += e00 + e01; rs1 += e10 + e11;
            __nv_bfloat162 h0 = __floats2bfloat162_rn(e00, e01);
            __nv_bfloat162 h1 = __floats2bfloat162_rn(e10, e11);
            *reinterpret_cast<uint32_t*>(f + ((size_t)z * SDIM + gr0) * SDIM + col) =
                *reinterpret_cast<uint32_t*>(&h0);
            *reinterpret_cast<uint32_t*>(f + ((size_t)z * SDIM + gr1) * SDIM + col) =
                *reinterpret_cast<uint32_t*>(&h1);
        }
        rs0 += __shfl_xor_sync(0xffffffffu, rs0, 1);
        rs0 += __shfl_xor_sync(0xffffffffu, rs0, 2);
        rs1 += __shfl_xor_sync(0xffffffffu, rs1, 1);
        rs1 += __shfl_xor_sync(0xffffffffu, rs1, 2);
        if ((lane & 3) == 0) {
            atomicAdd(&Z[(size_t)z * SDIM + gr0], rs0);
            atomicAdd(&Z[(size_t)z * SDIM + gr1], rs1);
        }
    }
}

// ============================ attend (HMMA, 512 thr, 128x256 tile, 3-stage) ============================
// smem: stage st -> A(128x64,16KB) @ st*49152, B(256x64,32KB) @ st*49152+16384
#define ASA(st) ((uint32_t)((st) * 49152))
#define ASB(st) ((uint32_t)((st) * 49152 + 16384))
__global__ __launch_bounds__(512)
void attend_hmma(const __nv_bfloat16* __restrict__ f,
                 const __nv_bfloat16* __restrict__ xb,
                 const float* __restrict__ Z,
                 __nv_bfloat16* __restrict__ y)
{
    extern __shared__ char smem[];
    const uint32_t sb = smem_u32(smem);
    const int tid = threadIdx.x, lane = tid & 31, wid = tid >> 5;
    const int wm = wid & 1, wn = wid >> 1;   // 2x8 warp grid: 64-row x 32-col warp tiles
    const int z = blockIdx.z, m0 = blockIdx.y * 128;

    const __nv_bfloat16* Abase = f + ((size_t)z * SDIM + m0) * SDIM;  // 128 rows, ld SDIM
    const __nv_bfloat16* Bbase = xb + (size_t)z * CDIM * SDIM;        // 256 rows, ld SDIM

    float acc[4][4][4];
    ZERO_ACC(acc);

    load_tileT<128, 512>(sb + ASA(0), Abase, SDIM);
    load_tileT<256, 512>(sb + ASB(0), Bbase, SDIM);
    CP_COMMIT();
    load_tileT<128, 512>(sb + ASA(1), Abase + 64, SDIM);
    load_tileT<256, 512>(sb + ASB(1), Bbase + 64, SDIM);
    CP_COMMIT();

    const int KT = SDIM / 64; // 64
    for (int kt = 0; kt < KT; kt++) {
        if (kt + 1 < KT) { CP_WAIT(1); } else { CP_WAIT(0); }
        __syncthreads();
        if (kt + 2 < KT) {
            const int st = (kt + 2) % 3;
            load_tileT<128, 512>(sb + ASA(st), Abase + (kt + 2) * 64, SDIM);
            load_tileT<256, 512>(sb + ASB(st), Bbase + (kt + 2) * 64, SDIM);
            CP_COMMIT();
        }
        compute_chunk(sb + ASA(kt % 3), sb + ASB(kt % 3), wm * 64, wn * 32, lane, acc);
    }

    const int lrow = lane >> 2, lcol2 = (lane & 3) * 2;
    #pragma unroll
    for (int mi = 0; mi < 4; mi++) {
        const int gr0 = m0 + wm * 64 + mi * 16 + lrow;
        const int gr1 = gr0 + 8;
        const float iz0 = 1.0f / Z[(size_t)z * SDIM + gr0];
        const float iz1 = 1.0f / Z[(size_t)z * SDIM + gr1];
        #pragma unroll
        for (int ni = 0; ni < 4; ni++) {
            const int col = wn * 32 + ni * 8 + lcol2;
            __nv_bfloat162 h0 = __floats2bfloat162_rn(acc[mi][ni][0] * iz0, acc[mi][ni][1] * iz0);
            __nv_bfloat162 h1 = __floats2bfloat162_rn(acc[mi][ni][2] * iz1, acc[mi][ni][3] * iz1);
            *reinterpret_cast<uint32_t*>(y + ((size_t)z * SDIM + gr0) * CDIM + col) =
                *reinterpret_cast<uint32_t*>(&h0);
            *reinterpret_cast<uint32_t*>(y + ((size_t)z * SDIM + gr1) * CDIM + col) =
                *reinterpret_cast<uint32_t*>(&h1);
        }
    }
}

// ============================ projection + residual (HMMA, 256 thr) ============================
__global__ __launch_bounds__(256)
void proj_hmma(const __nv_bfloat16* __restrict__ w3,
               const __nv_bfloat16* __restrict__ y,
               const float* __restrict__ x,
               float* __restrict__ out)
{
    extern __shared__ char smem[];
    const uint32_t sb = smem_u32(smem);
    const int tid = threadIdx.x, lane = tid & 31, wid = tid >> 5;
    const int wm = wid & 1, wn = wid >> 1;
    const int z = blockIdx.z, m0 = blockIdx.y * 128, n0 = blockIdx.x * 128;

    const __nv_bfloat16* Abase = w3 + (size_t)m0 * 256;
    const __nv_bfloat16* Bbase = y + ((size_t)z * SDIM + n0) * CDIM;

    float acc[4][4][4];
    ZERO_ACC(acc);

    load_tileT<128, 256>(sb + SA2(0), Abase, 256);
    load_tileT<128, 256>(sb + SB2(0), Bbase, 256);
    CP_COMMIT();

    const int KT = 4;
    #pragma unroll
    for (int kt = 0; kt < KT; kt++) {
        if (kt + 1 < KT) {
            load_tileT<128, 256>(sb + SA2((kt + 1) & 1), Abase + (kt + 1) * 64, 256);
            load_tileT<128, 256>(sb + SB2((kt + 1) & 1), Bbase + (kt + 1) * 64, 256);
            CP_COMMIT();
            CP_WAIT(1);
        } else {
            CP_WAIT(0);
        }
        __syncthreads();
        compute_chunk(sb + SA2(kt & 1), sb + SB2(kt & 1), wm * 64, wn * 32, lane, acc);
        __syncthreads();
    }

    const int lrow = lane >> 2, lcol2 = (lane & 3) * 2;
    #pragma unroll
    for (int mi = 0; mi < 4; mi++) {
        const int gr0 = m0 + wm * 64 + mi * 16 + lrow;
        const int gr1 = gr0 + 8;
        #pragma unroll
        for (int ni = 0; ni < 4; ni++) {
            const int col = n0 + wn * 32 + ni * 8 + lcol2;
            const float2 x0 = *reinterpret_cast<const float2*>(x + ((size_t)z * CDIM + gr0) * SDIM + col);
            const float2 x1 = *reinterpret_cast<const float2*>(x + ((size_t)z * CDIM + gr1) * SDIM + col);
            float2 v0 = make_float2(acc[mi][ni][0] + x0.x, acc[mi][ni][1] + x0.y);
            float2 v1 = make_float2(acc[mi][ni][2] + x1.x, acc[mi][ni][3] + x1.y);
            *reinterpret_cast<float2*>(out + ((size_t)z * CDIM + gr0) * SDIM + col) = v0;
            *reinterpret_cast<float2*>(out + ((size_t)z * CDIM + gr1) * SDIM + col) = v1;
        }
    }
}

// ============================ launch ============================
extern "C" void kernel_launch(void* const* d_in, const int* in_sizes, int n_in,
                              void* d_out, int out_size)
{
    const float* x       = (const float*)d_in[0];
    const float* theta_w = (const float*)d_in[1];
    const float* phi_w   = (const float*)d_in[2];
    const float* proj_w  = (const float*)d_in[3];
    float* out = (float*)d_out;

    __nv_bfloat16 *tp, *f, *xb, *yb, *w2, *w3;
    float *Z;
    cudaGetSymbolAddress((void**)&tp, g_tp);
    cudaGetSymbolAddress((void**)&f,  g_f);
    cudaGetSymbolAddress((void**)&xb, g_xb);
    cudaGetSymbolAddress((void**)&yb, g_yb);
    cudaGetSymbolAddress((void**)&w2, g_w2);
    cudaGetSymbolAddress((void**)&w3, g_w3);
    cudaGetSymbolAddress((void**)&Z,  g_Z);

    cudaFuncSetAttribute(thetaphi_hmma,   cudaFuncAttributeMaxDynamicSharedMemorySize, 65536);
    cudaFuncSetAttribute(logits_exp_hmma, cudaFuncAttributeMaxDynamicSharedMemorySize, 98304);
    cudaFuncSetAttribute(attend_hmma,     cudaFuncAttributeMaxDynamicSharedMemorySize, 147456);
    cudaFuncSetAttribute(proj_hmma,       cudaFuncAttributeMaxDynamicSharedMemorySize, 65536);

    // 0: bf16 conversions + Z zero
    prep_bf16<<<1024, 256>>>((const float4*)x, (const float4*)theta_w, (const float4*)phi_w,
                             (const float4*)proj_w, (uint2*)xb, (uint2*)w2, (uint2*)w3, Z,
                             (int)((size_t)NBATCH * CDIM * SDIM / 4));

    // 1: fused theta+phi projection
    thetaphi_hmma<<<dim3(2, 32, 4), 256, 65536>>>(xb, w2, tp);

    // 2: fused logits -> exp + row sums (256x128 tiles, 512 thr)
    logits_exp_hmma<<<dim3(32, 16, 4), 512, 98304>>>(tp, f, Z);

    // 3: attend + 1/Z (128x256 tiles, 512 thr, single wave)
    attend_hmma<<<dim3(1, 32, 4), 512, 147456>>>(f, xb, Z, yb);

    // 4: projection + residual
    proj_hmma<<<dim3(32, 2, 4), 256, 65536>>>(w3, yb, x, out);
}

// round 6
// speedup vs baseline: 1.0007x; 1.0007x over previous
#include <cuda_runtime.h>
#include <cuda_bf16.h>
#include <math.h>
#include <cstdint>

#define SDIM 4096
#define CDIM 256
#define EDIM 128
#define NBATCH 4

// ---- scratch (device globals: allocation-free) ----
__device__ __nv_bfloat16 g_tp[(size_t)NBATCH * SDIM * (2 * EDIM)]; // [n][s][0:128)=theta [128:256)=phi
__device__ __nv_bfloat16 g_f [(size_t)NBATCH * SDIM * SDIM];       // unnormalized exp(logits)
__device__ __nv_bfloat16 g_xb[(size_t)NBATCH * CDIM * SDIM];       // x bf16 [n][c][s]
__device__ __nv_bfloat16 g_yb[(size_t)NBATCH * SDIM * CDIM];       // y bf16 [n][s][c]
__device__ __nv_bfloat16 g_w2[256 * 256];                          // rows 0-127 theta_w, 128-255 phi_w
__device__ __nv_bfloat16 g_w3[256 * 256];                          // proj_w bf16 [o][c]
__device__ float         g_Z [(size_t)NBATCH * SDIM];              // row sums

// ============================ low-level helpers ============================
__device__ __forceinline__ uint32_t smem_u32(const void* p) {
    uint32_t a;
    asm("{ .reg .u64 t; cvta.to.shared.u64 t, %1; cvt.u32.u64 %0, t; }" : "=r"(a) : "l"(p));
    return a;
}
__device__ __forceinline__ void ldsm4(uint32_t r[4], uint32_t addr) {
    asm volatile("ldmatrix.sync.aligned.m8n8.x4.shared.b16 {%0,%1,%2,%3}, [%4];"
                 : "=r"(r[0]), "=r"(r[1]), "=r"(r[2]), "=r"(r[3]) : "r"(addr));
}
__device__ __forceinline__ void ldsm4t(uint32_t r[4], uint32_t addr) {
    asm volatile("ldmatrix.sync.aligned.m8n8.x4.trans.shared.b16 {%0,%1,%2,%3}, [%4];"
                 : "=r"(r[0]), "=r"(r[1]), "=r"(r[2]), "=r"(r[3]) : "r"(addr));
}
__device__ __forceinline__ void mma16816(float c[4], const uint32_t a[4], uint32_t b0, uint32_t b1) {
    asm volatile("mma.sync.aligned.m16n8k16.row.col.f32.bf16.bf16.f32 "
                 "{%0,%1,%2,%3},{%4,%5,%6,%7},{%8,%9},{%0,%1,%2,%3};"
                 : "+f"(c[0]), "+f"(c[1]), "+f"(c[2]), "+f"(c[3])
                 : "r"(a[0]), "r"(a[1]), "r"(a[2]), "r"(a[3]), "r"(b0), "r"(b1));
}
__device__ __forceinline__ void cp16(uint32_t saddr, const void* g) {
    asm volatile("cp.async.cg.shared.global [%0], [%1], 16;" :: "r"(saddr), "l"(g));
}
#define CP_COMMIT() asm volatile("cp.async.commit_group;" ::: "memory")
#define CP_WAIT(N)  asm volatile("cp.async.wait_group %0;" :: "n"(N) : "memory")

// R rows x 64 cols bf16 (128B rows), XOR-16B swizzle keyed on row&7. NT threads.
template<int R, int NT>
__device__ __forceinline__ void load_tileT(uint32_t sdst, const __nv_bfloat16* g, int ldg) {
    const int tid = threadIdx.x;
    #pragma unroll
    for (int i = 0; i < (R * 8) / NT; i++) {
        const int c = tid + i * NT;
        const int r = c >> 3, kc = c & 7;
        const uint32_t so = sdst + r * 128 + (((uint32_t)kc * 16) ^ ((r & 7) * 16));
        cp16(so, g + (size_t)r * ldg + kc * 8);
    }
}
// 64 rows x 128 cols bf16 (256B rows), 256 threads (trans-A path).
__device__ __forceinline__ void load_tile_64x128(uint32_t sdst, const __nv_bfloat16* g, int ldg) {
    const int tid = threadIdx.x;
    #pragma unroll
    for (int i = 0; i < 4; i++) {
        const int c = tid + i * 256;
        const int r = c >> 4, kc = c & 15;
        const uint32_t so = sdst + r * 256 + (((uint32_t)kc * 16) ^ ((r & 7) * 16));
        cp16(so, g + (size_t)r * ldg + kc * 8);
    }
}

// ---- 64x32 warp-tile chunk (legacy, used by small GEMMs) ----
__device__ __forceinline__ void compute_chunk(uint32_t sA, uint32_t sB,
                                              int m_base, int n_base, int lane,
                                              float acc[4][4][4]) {
    #pragma unroll
    for (int ks = 0; ks < 4; ks++) {
        const int kc = ks * 2 + (lane >> 4);
        uint32_t a[4][4];
        #pragma unroll
        for (int mi = 0; mi < 4; mi++) {
            const int row = m_base + mi * 16 + (lane & 15);
            ldsm4(a[mi], sA + row * 128 + (((uint32_t)kc * 16) ^ ((row & 7) * 16)));
        }
        uint32_t b[4][2];
        #pragma unroll
        for (int nh = 0; nh < 2; nh++) {
            const int row = n_base + nh * 16 + (lane & 15);
            uint32_t r4[4];
            ldsm4(r4, sB + row * 128 + (((uint32_t)kc * 16) ^ ((row & 7) * 16)));
            b[nh * 2 + 0][0] = r4[0]; b[nh * 2 + 0][1] = r4[2];
            b[nh * 2 + 1][0] = r4[1]; b[nh * 2 + 1][1] = r4[3];
        }
        #pragma unroll
        for (int mi = 0; mi < 4; mi++)
            #pragma unroll
            for (int ni = 0; ni < 4; ni++)
                mma16816(acc[mi][ni], a[mi], b[ni][0], b[ni][1]);
    }
}

// ---- 64x64 warp-tile chunk (big kernels): 8 LDSM -> 32 MMA per ks ----
__device__ __forceinline__ void compute_chunk64(uint32_t sA, uint32_t sB,
                                                int m_base, int n_base, int lane,
                                                float acc[4][8][4]) {
    #pragma unroll
    for (int ks = 0; ks < 4; ks++) {
        const int kc = ks * 2 + (lane >> 4);
        uint32_t a[4][4];
        #pragma unroll
        for (int mi = 0; mi < 4; mi++) {
            const int row = m_base + mi * 16 + (lane & 15);
            ldsm4(a[mi], sA + row * 128 + (((uint32_t)kc * 16) ^ ((row & 7) * 16)));
        }
        uint32_t b[8][2];
        #pragma unroll
        for (int nh = 0; nh < 4; nh++) {
            const int row = n_base + nh * 16 + (lane & 15);
            uint32_t r4[4];
            ldsm4(r4, sB + row * 128 + (((uint32_t)kc * 16) ^ ((row & 7) * 16)));
            b[nh * 2 + 0][0] = r4[0]; b[nh * 2 + 0][1] = r4[2];
            b[nh * 2 + 1][0] = r4[1]; b[nh * 2 + 1][1] = r4[3];
        }
        #pragma unroll
        for (int mi = 0; mi < 4; mi++)
            #pragma unroll
            for (int ni = 0; ni < 8; ni++)
                mma16816(acc[mi][ni], a[mi], b[ni][0], b[ni][1]);
    }
}

// trans-A chunk (thetaphi)
__device__ __forceinline__ void compute_chunk_At(uint32_t sA, uint32_t sB,
                                                 int wm, int wn, int lane,
                                                 float acc[4][4][4]) {
    #pragma unroll
    for (int ks = 0; ks < 4; ks++) {
        uint32_t a[4][4];
        const int crow_l = ks * 16 + (lane & 7) + ((lane >> 4) & 1) * 8;
        #pragma unroll
        for (int mi = 0; mi < 4; mi++) {
            const int scol = wm * 64 + mi * 16 + ((lane >> 3) & 1) * 8;
            ldsm4t(a[mi], sA + crow_l * 256 + ((((uint32_t)scol >> 3) * 16) ^ ((crow_l & 7) * 16)));
        }
        const int kc = ks * 2 + (lane >> 4);
        uint32_t b[4][2];
        #pragma unroll
        for (int nh = 0; nh < 2; nh++) {
            const int row = wn * 32 + nh * 16 + (lane & 15);
            uint32_t r4[4];
            ldsm4(r4, sB + row * 128 + (((uint32_t)kc * 16) ^ ((row & 7) * 16)));
            b[nh * 2 + 0][0] = r4[0]; b[nh * 2 + 0][1] = r4[2];
            b[nh * 2 + 1][0] = r4[1]; b[nh * 2 + 1][1] = r4[3];
        }
        #pragma unroll
        for (int mi = 0; mi < 4; mi++)
            #pragma unroll
            for (int ni = 0; ni < 4; ni++)
                mma16816(acc[mi][ni], a[mi], b[ni][0], b[ni][1]);
    }
}

#define ZERO_ACC4(acc) do { \
    _Pragma("unroll") for (int _a = 0; _a < 4; _a++) \
    _Pragma("unroll") for (int _b = 0; _b < 4; _b++) \
    _Pragma("unroll") for (int _c = 0; _c < 4; _c++) acc[_a][_b][_c] = 0.0f; } while (0)
#define ZERO_ACC8(acc) do { \
    _Pragma("unroll") for (int _a = 0; _a < 4; _a++) \
    _Pragma("unroll") for (int _b = 0; _b < 8; _b++) \
    _Pragma("unroll") for (int _c = 0; _c < 4; _c++) acc[_a][_b][_c] = 0.0f; } while (0)

// ============================ prep ============================
__global__ __launch_bounds__(256) void prep_bf16(const float4* __restrict__ x,
                                                 const float4* __restrict__ theta_w,
                                                 const float4* __restrict__ phi_w,
                                                 const float4* __restrict__ proj_w,
                                                 uint2* __restrict__ xb,
                                                 uint2* __restrict__ w2,
                                                 uint2* __restrict__ w3,
                                                 float* __restrict__ Z, int n4)
{
    const int gt = blockIdx.x * blockDim.x + threadIdx.x;
    const int stride = gridDim.x * blockDim.x;
    if (gt < NBATCH * SDIM) Z[gt] = 0.0f;
    for (int i = gt; i < n4; i += stride) {
        float4 v = x[i];
        __nv_bfloat162 a = __floats2bfloat162_rn(v.x, v.y);
        __nv_bfloat162 b = __floats2bfloat162_rn(v.z, v.w);
        xb[i] = make_uint2(*reinterpret_cast<uint32_t*>(&a), *reinterpret_cast<uint32_t*>(&b));
    }
    if (gt < 8192) {
        float4 v = theta_w[gt];
        __nv_bfloat162 a = __floats2bfloat162_rn(v.x, v.y);
        __nv_bfloat162 b = __floats2bfloat162_rn(v.z, v.w);
        w2[gt] = make_uint2(*reinterpret_cast<uint32_t*>(&a), *reinterpret_cast<uint32_t*>(&b));
        v = phi_w[gt];
        a = __floats2bfloat162_rn(v.x, v.y);
        b = __floats2bfloat162_rn(v.z, v.w);
        w2[8192 + gt] = make_uint2(*reinterpret_cast<uint32_t*>(&a), *reinterpret_cast<uint32_t*>(&b));
    }
    if (gt < 16384) {
        float4 v = proj_w[gt];
        __nv_bfloat162 a = __floats2bfloat162_rn(v.x, v.y);
        __nv_bfloat162 b = __floats2bfloat162_rn(v.z, v.w);
        w3[gt] = make_uint2(*reinterpret_cast<uint32_t*>(&a), *reinterpret_cast<uint32_t*>(&b));
    }
}

// ============================ theta/phi projection (HMMA trans-A, 256 thr) ============================
#define SA2(st) ((uint32_t)((st) * 32768))
#define SB2(st) ((uint32_t)((st) * 32768 + 16384))
__global__ __launch_bounds__(256)
void thetaphi_hmma(const __nv_bfloat16* __restrict__ xb,
                   const __nv_bfloat16* __restrict__ w2,
                   __nv_bfloat16* __restrict__ tp)
{
    extern __shared__ char smem[];
    const uint32_t sb = smem_u32(smem);
    const int tid = threadIdx.x, lane = tid & 31, wid = tid >> 5;
    const int wm = wid & 1, wn = wid >> 1;
    const int z = blockIdx.z, m0 = blockIdx.y * 128, n0 = blockIdx.x * 128;

    const __nv_bfloat16* Abase = xb + (size_t)z * CDIM * SDIM + m0;
    const __nv_bfloat16* Bbase = w2 + (size_t)n0 * 256;

    float acc[4][4][4];
    ZERO_ACC4(acc);

    load_tile_64x128(sb + SA2(0), Abase, SDIM);
    load_tileT<128, 256>(sb + SB2(0), Bbase, 256);
    CP_COMMIT();

    const int KT = 4;
    #pragma unroll
    for (int kt = 0; kt < KT; kt++) {
        if (kt + 1 < KT) {
            load_tile_64x128(sb + SA2((kt + 1) & 1), Abase + (size_t)(kt + 1) * 64 * SDIM, SDIM);
            load_tileT<128, 256>(sb + SB2((kt + 1) & 1), Bbase + (kt + 1) * 64, 256);
            CP_COMMIT();
            CP_WAIT(1);
        } else {
            CP_WAIT(0);
        }
        __syncthreads();
        compute_chunk_At(sb + SA2(kt & 1), sb + SB2(kt & 1), wm, wn, lane, acc);
        __syncthreads();
    }

    const int lrow = lane >> 2, lcol2 = (lane & 3) * 2;
    #pragma unroll
    for (int mi = 0; mi < 4; mi++) {
        const int gr0 = m0 + wm * 64 + mi * 16 + lrow;
        #pragma unroll
        for (int ni = 0; ni < 4; ni++) {
            const int col = n0 + wn * 32 + ni * 8 + lcol2;
            __nv_bfloat162 h0 = __floats2bfloat162_rn(acc[mi][ni][0], acc[mi][ni][1]);
            __nv_bfloat162 h1 = __floats2bfloat162_rn(acc[mi][ni][2], acc[mi][ni][3]);
            *reinterpret_cast<uint32_t*>(tp + ((size_t)z * SDIM + gr0) * 256 + col) =
                *reinterpret_cast<uint32_t*>(&h0);
            *reinterpret_cast<uint32_t*>(tp + ((size_t)z * SDIM + gr0 + 8) * 256 + col) =
                *reinterpret_cast<uint32_t*>(&h1);
        }
    }
}

// ============================ fused logits + exp (HMMA, 256 thr, 128x256 tile, 64x64 warp) ============================
// smem: A0 @0, A1 @16K (theta 128x64 each); B0 @32K, B1 @64K (phi 256x64 each). 96KB total.
__global__ __launch_bounds__(256)
void logits_exp_hmma(const __nv_bfloat16* __restrict__ tp,
                     __nv_bfloat16* __restrict__ f,
                     float* __restrict__ Z)
{
    extern __shared__ char smem[];
    const uint32_t sb = smem_u32(smem);
    const int tid = threadIdx.x, lane = tid & 31, wid = tid >> 5;
    const int wm = wid & 1, wn = wid >> 1;  // 2x4 grid of 64x64 warp tiles
    const int z = blockIdx.z, m0 = blockIdx.y * 128, n0 = blockIdx.x * 256;

    const __nv_bfloat16* Abase = tp + ((size_t)(z * SDIM + m0)) * 256;        // theta 128 rows
    const __nv_bfloat16* Bbase = tp + ((size_t)(z * SDIM + n0)) * 256 + 128;  // phi 256 rows

    float acc[4][8][4];
    ZERO_ACC8(acc);

    load_tileT<128, 256>(sb + 0,     Abase, 256);
    load_tileT<128, 256>(sb + 16384, Abase + 64, 256);
    load_tileT<256, 256>(sb + 32768, Bbase, 256);
    load_tileT<256, 256>(sb + 65536, Bbase + 64, 256);
    CP_COMMIT();
    CP_WAIT(0);
    __syncthreads();

    compute_chunk64(sb + 0,     sb + 32768, wm * 64, wn * 64, lane, acc);
    compute_chunk64(sb + 16384, sb + 65536, wm * 64, wn * 64, lane, acc);

    const float alpha = 0.08838834764831845f; // 1/sqrt(128)
    const int lrow = lane >> 2, lcol2 = (lane & 3) * 2;
    #pragma unroll
    for (int mi = 0; mi < 4; mi++) {
        const int gr0 = m0 + wm * 64 + mi * 16 + lrow;
        const int gr1 = gr0 + 8;
        float rs0 = 0.0f, rs1 = 0.0f;
        #pragma unroll
        for (int ni = 0; ni < 8; ni++) {
            const int col = n0 + wn * 64 + ni * 8 + lcol2;
            float e00 = __expf(acc[mi][ni][0] * alpha);
            float e01 = __expf(acc[mi][ni][1] * alpha);
            float e10 = __expf(acc[mi][ni][2] * alpha);
            float e11 = __expf(acc[mi][ni][3] * alpha);
            rs0 += e00 + e01; rs1 += e10 + e11;
            __nv_bfloat162 h0 = __floats2bfloat162_rn(e00, e01);
            __nv_bfloat162 h1 = __floats2bfloat162_rn(e10, e11);
            *reinterpret_cast<uint32_t*>(f + ((size_t)z * SDIM + gr0) * SDIM + col) =
                *reinterpret_cast<uint32_t*>(&h0);
            *reinterpret_cast<uint32_t*>(f + ((size_t)z * SDIM + gr1) * SDIM + col) =
                *reinterpret_cast<uint32_t*>(&h1);
        }
        rs0 += __shfl_xor_sync(0xffffffffu, rs0, 1);
        rs0 += __shfl_xor_sync(0xffffffffu, rs0, 2);
        rs1 += __shfl_xor_sync(0xffffffffu, rs1, 1);
        rs1 += __shfl_xor_sync(0xffffffffu, rs1, 2);
        if ((lane & 3) == 0) {
            atomicAdd(&Z[(size_t)z * SDIM + gr0], rs0);
            atomicAdd(&Z[(size_t)z * SDIM + gr1], rs1);
        }
    }
}

// ============================ attend (HMMA, 256 thr, 128x256 tile, 64x64 warp, 3-stage) ============================
// smem: stage st -> A(128x64,16KB) @ st*49152, B(256x64,32KB) @ st*49152+16384. 144KB.
#define ASA(st) ((uint32_t)((st) * 49152))
#define ASB(st) ((uint32_t)((st) * 49152 + 16384))
__global__ __launch_bounds__(256)
void attend_hmma(const __nv_bfloat16* __restrict__ f,
                 const __nv_bfloat16* __restrict__ xb,
                 const float* __restrict__ Z,
                 __nv_bfloat16* __restrict__ y)
{
    extern __shared__ char smem[];
    const uint32_t sb = smem_u32(smem);
    const int tid = threadIdx.x, lane = tid & 31, wid = tid >> 5;
    const int wm = wid & 1, wn = wid >> 1;  // 2x4 grid of 64x64 warp tiles
    const int z = blockIdx.z, m0 = blockIdx.y * 128;

    const __nv_bfloat16* Abase = f + ((size_t)z * SDIM + m0) * SDIM;  // 128 rows
    const __nv_bfloat16* Bbase = xb + (size_t)z * CDIM * SDIM;        // 256 rows

    float acc[4][8][4];
    ZERO_ACC8(acc);

    load_tileT<128, 256>(sb + ASA(0), Abase, SDIM);
    load_tileT<256, 256>(sb + ASB(0), Bbase, SDIM);
    CP_COMMIT();
    load_tileT<128, 256>(sb + ASA(1), Abase + 64, SDIM);
    load_tileT<256, 256>(sb + ASB(1), Bbase + 64, SDIM);
    CP_COMMIT();

    const int KT = SDIM / 64; // 64
    for (int kt = 0; kt < KT; kt++) {
        if (kt + 1 < KT) { CP_WAIT(1); } else { CP_WAIT(0); }
        __syncthreads();
        if (kt + 2 < KT) {
            const int st = (kt + 2) % 3;
            load_tileT<128, 256>(sb + ASA(st), Abase + (kt + 2) * 64, SDIM);
            load_tileT<256, 256>(sb + ASB(st), Bbase + (kt + 2) * 64, SDIM);
            CP_COMMIT();
        }
        compute_chunk64(sb + ASA(kt % 3), sb + ASB(kt % 3), wm * 64, wn * 64, lane, acc);
    }

    const int lrow = lane >> 2, lcol2 = (lane & 3) * 2;
    #pragma unroll
    for (int mi = 0; mi < 4; mi++) {
        const int gr0 = m0 + wm * 64 + mi * 16 + lrow;
        const int gr1 = gr0 + 8;
        const float iz0 = 1.0f / Z[(size_t)z * SDIM + gr0];
        const float iz1 = 1.0f / Z[(size_t)z * SDIM + gr1];
        #pragma unroll
        for (int ni = 0; ni < 8; ni++) {
            const int col = wn * 64 + ni * 8 + lcol2;
            __nv_bfloat162 h0 = __floats2bfloat162_rn(acc[mi][ni][0] * iz0, acc[mi][ni][1] * iz0);
            __nv_bfloat162 h1 = __floats2bfloat162_rn(acc[mi][ni][2] * iz1, acc[mi][ni][3] * iz1);
            *reinterpret_cast<uint32_t*>(y + ((size_t)z * SDIM + gr0) * CDIM + col) =
                *reinterpret_cast<uint32_t*>(&h0);
            *reinterpret_cast<uint32_t*>(y + ((size_t)z * SDIM + gr1) * CDIM + col) =
                *reinterpret_cast<uint32_t*>(&h1);
        }
    }
}

// ============================ projection + residual (HMMA, 256 thr) ============================
__global__ __launch_bounds__(256)
void proj_hmma(const __nv_bfloat16* __restrict__ w3,
               const __nv_bfloat16* __restrict__ y,
               const float* __restrict__ x,
               float* __restrict__ out)
{
    extern __shared__ char smem[];
    const uint32_t sb = smem_u32(smem);
    const int tid = threadIdx.x, lane = tid & 31, wid = tid >> 5;
    const int wm = wid & 1, wn = wid >> 1;
    const int z = blockIdx.z, m0 = blockIdx.y * 128, n0 = blockIdx.x * 128;

    const __nv_bfloat16* Abase = w3 + (size_t)m0 * 256;
    const __nv_bfloat16* Bbase = y + ((size_t)z * SDIM + n0) * CDIM;

    float acc[4][4][4];
    ZERO_ACC4(acc);

    load_tileT<128, 256>(sb + SA2(0), Abase, 256);
    load_tileT<128, 256>(sb + SB2(0), Bbase, 256);
    CP_COMMIT();

    const int KT = 4;
    #pragma unroll
    for (int kt = 0; kt < KT; kt++) {
        if (kt + 1 < KT) {
            load_tileT<128, 256>(sb + SA2((kt + 1) & 1), Abase + (kt + 1) * 64, 256);
            load_tileT<128, 256>(sb + SB2((kt + 1) & 1), Bbase + (kt + 1) * 64, 256);
            CP_COMMIT();
            CP_WAIT(1);
        } else {
            CP_WAIT(0);
        }
        __syncthreads();
        compute_chunk(sb + SA2(kt & 1), sb + SB2(kt & 1), wm * 64, wn * 32, lane, acc);
        __syncthreads();
    }

    const int lrow = lane >> 2, lcol2 = (lane & 3) * 2;
    #pragma unroll
    for (int mi = 0; mi < 4; mi++) {
        const int gr0 = m0 + wm * 64 + mi * 16 + lrow;
        const int gr1 = gr0 + 8;
        #pragma unroll
        for (int ni = 0; ni < 4; ni++) {
            const int col = n0 + wn * 32 + ni * 8 + lcol2;
            const float2 x0 = *reinterpret_cast<const float2*>(x + ((size_t)z * CDIM + gr0) * SDIM + col);
            const float2 x1 = *reinterpret_cast<const float2*>(x + ((size_t)z * CDIM + gr1) * SDIM + col);
            float2 v0 = make_float2(acc[mi][ni][0] + x0.x, acc[mi][ni][1] + x0.y);
            float2 v1 = make_float2(acc[mi][ni][2] + x1.x, acc[mi][ni][3] + x1.y);
            *reinterpret_cast<float2*>(out + ((size_t)z * CDIM + gr0) * SDIM + col) = v0;
            *reinterpret_cast<float2*>(out + ((size_t)z * CDIM + gr1) * SDIM + col) = v1;
        }
    }
}

// ============================ launch ============================
extern "C" void kernel_launch(void* const* d_in, const int* in_sizes, int n_in,
                              void* d_out, int out_size)
{
    const float* x       = (const float*)d_in[0];
    const float* theta_w = (const float*)d_in[1];
    const float* phi_w   = (const float*)d_in[2];
    const float* proj_w  = (const float*)d_in[3];
    float* out = (float*)d_out;

    __nv_bfloat16 *tp, *f, *xb, *yb, *w2, *w3;
    float *Z;
    cudaGetSymbolAddress((void**)&tp, g_tp);
    cudaGetSymbolAddress((void**)&f,  g_f);
    cudaGetSymbolAddress((void**)&xb, g_xb);
    cudaGetSymbolAddress((void**)&yb, g_yb);
    cudaGetSymbolAddress((void**)&w2, g_w2);
    cudaGetSymbolAddress((void**)&w3, g_w3);
    cudaGetSymbolAddress((void**)&Z,  g_Z);

    cudaFuncSetAttribute(thetaphi_hmma,   cudaFuncAttributeMaxDynamicSharedMemorySize, 65536);
    cudaFuncSetAttribute(logits_exp_hmma, cudaFuncAttributeMaxDynamicSharedMemorySize, 98304);
    cudaFuncSetAttribute(attend_hmma,     cudaFuncAttributeMaxDynamicSharedMemorySize, 147456);
    cudaFuncSetAttribute(proj_hmma,       cudaFuncAttributeMaxDynamicSharedMemorySize, 65536);

    // 0: bf16 conversions + Z zero
    prep_bf16<<<1024, 256>>>((const float4*)x, (const float4*)theta_w, (const float4*)phi_w,
                             (const float4*)proj_w, (uint2*)xb, (uint2*)w2, (uint2*)w3, Z,
                             (int)((size_t)NBATCH * CDIM * SDIM / 4));

    // 1: fused theta+phi projection
    thetaphi_hmma<<<dim3(2, 32, 4), 256, 65536>>>(xb, w2, tp);

    // 2: fused logits -> exp + row sums (128x256 tiles, 64x64 warp tiles)
    logits_exp_hmma<<<dim3(16, 32, 4), 256, 98304>>>(tp, f, Z);

    // 3: attend + 1/Z (128x256 tiles, 64x64 warp tiles, single wave)
    attend_hmma<<<dim3(1, 32, 4), 256, 147456>>>(f, xb, Z, yb);

    // 4: projection + residual
    proj_hmma<<<dim3(32, 2, 4), 256, 65536>>>(w3, yb, x, out);
}